// round 2
// baseline (speedup 1.0000x reference)
#include <cuda_runtime.h>
#include <math_constants.h>

// Problem constants: B=4, H=16, S=2048, D=64, fp32.
#define NBH     64          // B*H
#define SEQ     2048
#define HD      64
#define BR      64          // q rows per block
#define BC      64          // k cols per tile
#define NTILES  (SEQ / BC)  // 32
#define NQT     (SEQ / BR)  // 32
#define NTHREADS 256

// 1/sqrt(64) * log2(e)
#define SCALE_LOG2E 0.18033688011112042f

__device__ __forceinline__ float ex2f(float x) {
    float y;
    asm("ex2.approx.ftz.f32 %0, %1;" : "=f"(y) : "f"(x));
    return y;
}

// Load a 64x64 fp32 tile (global row-major, rows contiguous => 1024 float4 flat)
// into smem with chunk swizzle: chunk' = chunk ^ ((row>>2)&7).
__device__ __forceinline__ void load_tile(float4* __restrict__ dst,
                                          const float4* __restrict__ src,
                                          int tid) {
#pragma unroll
    for (int k = 0; k < 4; ++k) {
        int idx  = tid + k * NTHREADS;   // 0..1023
        int row  = idx >> 4;
        int ch   = idx & 15;
        dst[(row << 4) | (ch ^ ((row >> 2) & 7))] = src[idx];
    }
}

extern __shared__ float4 smem4[];

__global__ void __launch_bounds__(NTHREADS, 2)
fa_fwd_kernel(const float* __restrict__ q,
              const float* __restrict__ k,
              const float* __restrict__ v,
              float* __restrict__ o) {
    const int qt  = blockIdx.x;   // q tile index
    const int bh  = blockIdx.y;   // (b,h) index
    const int tid = threadIdx.x;
    const int tx  = tid & 15;     // 16 threads across 64 output cols (4 each)
    const int ty  = tid >> 4;     // 16 thread-groups across 64 rows (4 each)

    float4* sQ = smem4;           // 1024 float4 = 16 KB
    float4* sK = sQ + 1024;
    float4* sV = sK + 1024;
    float4* sP = sV + 1024;

    const size_t head_off = (size_t)bh * SEQ * HD;

    load_tile(sQ, (const float4*)(q + head_off + (size_t)qt * BR * HD), tid);

    float m[4], l[4], acc_o[4][4];
#pragma unroll
    for (int i = 0; i < 4; ++i) {
        m[i] = -CUDART_INF_F;
        l[i] = 0.0f;
#pragma unroll
        for (int j = 0; j < 4; ++j) acc_o[i][j] = 0.0f;
    }

    const int swa = ty & 7;   // swizzle const for rows 4*ty+i  ((row>>2)&7 == ty&7)
    const int swb = tx & 7;   // swizzle const for rows 4*tx+j

    for (int t = 0; t < NTILES; ++t) {
        __syncthreads();  // previous iteration done reading sK/sV/sP
        load_tile(sK, (const float4*)(k + head_off + (size_t)t * BC * HD), tid);
        load_tile(sV, (const float4*)(v + head_off + (size_t)t * BC * HD), tid);
        __syncthreads();

        // ---- GEMM1: S = Q @ K^T  (4x4 micro-tile per thread) ----
        float acc_s[4][4];
#pragma unroll
        for (int i = 0; i < 4; ++i)
#pragma unroll
            for (int j = 0; j < 4; ++j) acc_s[i][j] = 0.0f;

#pragma unroll
        for (int d4 = 0; d4 < 16; ++d4) {
            float4 a[4], b[4];
#pragma unroll
            for (int i = 0; i < 4; ++i)
                a[i] = sQ[((4 * ty + i) << 4) | (d4 ^ swa)];
#pragma unroll
            for (int j = 0; j < 4; ++j)
                b[j] = sK[((4 * tx + j) << 4) | (d4 ^ swb)];
#pragma unroll
            for (int i = 0; i < 4; ++i)
#pragma unroll
                for (int j = 0; j < 4; ++j) {
                    acc_s[i][j] = fmaf(a[i].x, b[j].x, acc_s[i][j]);
                    acc_s[i][j] = fmaf(a[i].y, b[j].y, acc_s[i][j]);
                    acc_s[i][j] = fmaf(a[i].z, b[j].z, acc_s[i][j]);
                    acc_s[i][j] = fmaf(a[i].w, b[j].w, acc_s[i][j]);
                }
        }

        // ---- Online softmax (row stats replicated in registers across the
        //      16-thread row group via half-warp shuffles) ----
#pragma unroll
        for (int i = 0; i < 4; ++i) {
            float rmax = fmaxf(fmaxf(acc_s[i][0], acc_s[i][1]),
                               fmaxf(acc_s[i][2], acc_s[i][3]));
#pragma unroll
            for (int off = 8; off >= 1; off >>= 1)
                rmax = fmaxf(rmax, __shfl_xor_sync(0xffffffffu, rmax, off));

            float mn    = fmaxf(m[i], rmax);
            float alpha = ex2f((m[i] - mn) * SCALE_LOG2E);

            float rsum = 0.0f;
#pragma unroll
            for (int j = 0; j < 4; ++j) {
                float p = ex2f((acc_s[i][j] - mn) * SCALE_LOG2E);
                acc_s[i][j] = p;
                rsum += p;
            }
#pragma unroll
            for (int off = 8; off >= 1; off >>= 1)
                rsum += __shfl_xor_sync(0xffffffffu, rsum, off);

            l[i] = l[i] * alpha + rsum;
            m[i] = mn;
#pragma unroll
            for (int j = 0; j < 4; ++j) acc_o[i][j] *= alpha;

            // write P row fragment (cols 4*tx..4*tx+3 of row 4*ty+i)
            sP[((4 * ty + i) << 4) | (tx ^ swa)] =
                make_float4(acc_s[i][0], acc_s[i][1], acc_s[i][2], acc_s[i][3]);
        }
        __syncthreads();  // P fully written

        // ---- GEMM2: O += P @ V ----
#pragma unroll
        for (int c4 = 0; c4 < 16; ++c4) {
            float4 a[4];
#pragma unroll
            for (int i = 0; i < 4; ++i)
                a[i] = sP[((4 * ty + i) << 4) | (c4 ^ swa)];
#pragma unroll
            for (int jj = 0; jj < 4; ++jj) {
                float4 b = sV[((4 * c4 + jj) << 4) | (tx ^ (c4 & 7))];
#pragma unroll
                for (int i = 0; i < 4; ++i) {
                    float av = (jj == 0) ? a[i].x : (jj == 1) ? a[i].y
                             : (jj == 2) ? a[i].z : a[i].w;
                    acc_o[i][0] = fmaf(av, b.x, acc_o[i][0]);
                    acc_o[i][1] = fmaf(av, b.y, acc_o[i][1]);
                    acc_o[i][2] = fmaf(av, b.z, acc_o[i][2]);
                    acc_o[i][3] = fmaf(av, b.w, acc_o[i][3]);
                }
            }
        }
    }

    // ---- Epilogue: normalize by l and store ----
    float4* og = (float4*)(o + head_off + (size_t)qt * BR * HD);
#pragma unroll
    for (int i = 0; i < 4; ++i) {
        float rl = 1.0f / l[i];
        og[(4 * ty + i) * 16 + tx] = make_float4(acc_o[i][0] * rl,
                                                 acc_o[i][1] * rl,
                                                 acc_o[i][2] * rl,
                                                 acc_o[i][3] * rl);
    }
}

extern "C" void kernel_launch(void* const* d_in, const int* in_sizes, int n_in,
                              void* d_out, int out_size) {
    const float* q = (const float*)d_in[0];
    const float* k = (const float*)d_in[1];
    const float* v = (const float*)d_in[2];
    float* o = (float*)d_out;

    const int smem_bytes = 4 * 64 * 64 * (int)sizeof(float);  // 64 KB dynamic
    cudaFuncSetAttribute(fa_fwd_kernel,
                         cudaFuncAttributeMaxDynamicSharedMemorySize, smem_bytes);

    dim3 grid(NQT, NBH);   // 32 x 64 = 2048 blocks
    fa_fwd_kernel<<<grid, NTHREADS, smem_bytes>>>(q, k, v, o);
}

// round 4
// speedup vs baseline: 3.3129x; 3.3129x over previous
#include <cuda_runtime.h>
#include <cstdint>
#include <math_constants.h>

// B=4, H=16, S=2048, D=64, fp32 in/out.
#define NBH      64
#define SEQ      2048
#define HD       64
#define BR       128        // q rows per CTA (4 warps x 32 rows)
#define BC       64         // kv rows per tile
#define NT       (SEQ/BC)   // 32
#define NTHREADS 128
#define STK      68         // K smem row stride (floats): bank = 4g+tg, conflict-free
#define STV      72         // V smem row stride: bank = 8tg+g, conflict-free
#define STP      68         // P smem row stride

// (1/sqrt(64)) * log2(e)
#define SCALE_LOG2E 0.18033688011112042f

__device__ __forceinline__ float ex2f(float x) {
    float y; asm("ex2.approx.ftz.f32 %0, %1;" : "=f"(y) : "f"(x)); return y;
}
__device__ __forceinline__ uint32_t cvt_tf32(float x) {
    uint32_t r; asm("cvt.rna.tf32.f32 %0, %1;" : "=r"(r) : "f"(x)); return r;
}
__device__ __forceinline__ void mma_tf32(float* d, const uint32_t* a,
                                         uint32_t b0, uint32_t b1) {
    asm volatile(
        "mma.sync.aligned.m16n8k8.row.col.f32.tf32.tf32.f32 "
        "{%0,%1,%2,%3}, {%4,%5,%6,%7}, {%8,%9}, {%0,%1,%2,%3};\n"
        : "+f"(d[0]), "+f"(d[1]), "+f"(d[2]), "+f"(d[3])
        : "r"(a[0]), "r"(a[1]), "r"(a[2]), "r"(a[3]), "r"(b0), "r"(b1));
}
__device__ __forceinline__ void cp_async16(float* smem_dst, const float* gmem_src) {
    uint32_t s = (uint32_t)__cvta_generic_to_shared(smem_dst);
    asm volatile("cp.async.cg.shared.global [%0], [%1], 16;\n" :: "r"(s), "l"(gmem_src));
}

extern __shared__ float smem[];

__global__ void __launch_bounds__(NTHREADS, 2)
fa_tf32_kernel(const float* __restrict__ q, const float* __restrict__ k,
               const float* __restrict__ v, float* __restrict__ o)
{
    const int qt  = blockIdx.x;
    const int bh  = blockIdx.y;
    const int tid = threadIdx.x;
    const int w   = tid >> 5;
    const int lane = tid & 31;
    const int g   = lane >> 2;   // group id (0..7)
    const int tg  = lane & 3;    // thread in group (0..3)

    float* sK = smem;                          // 2 x 64 x STK
    float* sV = smem + 2 * 64 * STK;           // 2 x 64 x STV
    float* sP = smem + 2 * 64 * STK + 2 * 64 * STV;  // 128 x STP (also Q staging)

    const size_t hoff = (size_t)bh * SEQ * HD;
    const float* qg = q + hoff + (size_t)qt * BR * HD;
    const float* kg = k + hoff;
    const float* vg = v + hoff;

    // ---- stage Q tile into sP (coalesced) ----
#pragma unroll
    for (int i = 0; i < 16; ++i) {
        int idx = tid + i * NTHREADS;         // 0..2047 float4s
        int r = idx >> 4, c4 = idx & 15;
        *(float4*)(sP + r * STP + c4 * 4) = *(const float4*)(qg + r * HD + c4 * 4);
    }
    // ---- prefetch tile 0 (K,V) into buffer 0 ----
#pragma unroll
    for (int i = 0; i < 8; ++i) {
        int idx = tid + i * NTHREADS;         // 0..1023
        int r = idx >> 4, c4 = idx & 15;
        cp_async16(sK + r * STK + c4 * 4, kg + r * HD + c4 * 4);
    }
#pragma unroll
    for (int i = 0; i < 8; ++i) {
        int idx = tid + i * NTHREADS;
        int r = idx >> 4, c4 = idx & 15;
        cp_async16(sV + r * STV + c4 * 4, vg + r * HD + c4 * 4);
    }
    asm volatile("cp.async.commit_group;\n");
    __syncthreads();   // Q staged & visible

    // ---- Q fragments, register-resident (tf32, RN-converted) ----
    uint32_t qa[2][8][4];
#pragma unroll
    for (int bnd = 0; bnd < 2; ++bnd) {
        const float* qr0 = sP + (w * 32 + bnd * 16 + g) * STP;
        const float* qr1 = qr0 + 8 * STP;
#pragma unroll
        for (int kk = 0; kk < 8; ++kk) {
            qa[bnd][kk][0] = cvt_tf32(qr0[kk * 8 + tg]);
            qa[bnd][kk][1] = cvt_tf32(qr1[kk * 8 + tg]);
            qa[bnd][kk][2] = cvt_tf32(qr0[kk * 8 + tg + 4]);
            qa[bnd][kk][3] = cvt_tf32(qr1[kk * 8 + tg + 4]);
        }
    }

    float acc_o[2][8][4];
    float m[2][2], l[2][2];
#pragma unroll
    for (int bnd = 0; bnd < 2; ++bnd) {
        m[bnd][0] = -CUDART_INF_F; m[bnd][1] = -CUDART_INF_F;
        l[bnd][0] = 0.0f;          l[bnd][1] = 0.0f;
#pragma unroll
        for (int n0 = 0; n0 < 8; ++n0)
#pragma unroll
            for (int j = 0; j < 4; ++j) acc_o[bnd][n0][j] = 0.0f;
    }

    for (int t = 0; t < NT; ++t) {
        __syncthreads();  // all warps done with previous compute (buffer (t+1)&1 free)

        if (t + 1 < NT) {
            const float* kgt = kg + (size_t)(t + 1) * BC * HD;
            const float* vgt = vg + (size_t)(t + 1) * BC * HD;
            float* skb = sK + ((t + 1) & 1) * (64 * STK);
            float* svb = sV + ((t + 1) & 1) * (64 * STV);
#pragma unroll
            for (int i = 0; i < 8; ++i) {
                int idx = tid + i * NTHREADS;
                int r = idx >> 4, c4 = idx & 15;
                cp_async16(skb + r * STK + c4 * 4, kgt + r * HD + c4 * 4);
            }
#pragma unroll
            for (int i = 0; i < 8; ++i) {
                int idx = tid + i * NTHREADS;
                int r = idx >> 4, c4 = idx & 15;
                cp_async16(svb + r * STV + c4 * 4, vgt + r * HD + c4 * 4);
            }
            asm volatile("cp.async.commit_group;\n");
            asm volatile("cp.async.wait_group 1;\n");   // tile t's group complete
        } else {
            asm volatile("cp.async.wait_group 0;\n");
        }
        __syncthreads();  // tile t visible to all

        const float* skb = sK + (t & 1) * (64 * STK);
        const float* svb = sV + (t & 1) * (64 * STV);

        // ---- GEMM1: S = Q @ K^T  (tensor cores) ----
        float acc_s[2][8][4];
#pragma unroll
        for (int bnd = 0; bnd < 2; ++bnd)
#pragma unroll
            for (int n0 = 0; n0 < 8; ++n0)
#pragma unroll
                for (int j = 0; j < 4; ++j) acc_s[bnd][n0][j] = 0.0f;

#pragma unroll
        for (int n0 = 0; n0 < 8; ++n0) {
            const float* kb = skb + (n0 * 8 + g) * STK + tg;
#pragma unroll
            for (int kk = 0; kk < 8; ++kk) {
                uint32_t b0 = cvt_tf32(kb[kk * 8]);
                uint32_t b1 = cvt_tf32(kb[kk * 8 + 4]);
                mma_tf32(acc_s[0][n0], qa[0][kk], b0, b1);
                mma_tf32(acc_s[1][n0], qa[1][kk], b0, b1);
            }
        }

        // ---- online softmax (rows: band*16 + g and +8; quad = lanes sharing g) ----
        float mn[2][2], alpha[2][2];
#pragma unroll
        for (int bnd = 0; bnd < 2; ++bnd) {
            float r0 = -CUDART_INF_F, r1 = -CUDART_INF_F;
#pragma unroll
            for (int n0 = 0; n0 < 8; ++n0) {
                r0 = fmaxf(r0, fmaxf(acc_s[bnd][n0][0], acc_s[bnd][n0][1]));
                r1 = fmaxf(r1, fmaxf(acc_s[bnd][n0][2], acc_s[bnd][n0][3]));
            }
            r0 = fmaxf(r0, __shfl_xor_sync(0xffffffffu, r0, 1));
            r0 = fmaxf(r0, __shfl_xor_sync(0xffffffffu, r0, 2));
            r1 = fmaxf(r1, __shfl_xor_sync(0xffffffffu, r1, 1));
            r1 = fmaxf(r1, __shfl_xor_sync(0xffffffffu, r1, 2));
            mn[bnd][0] = fmaxf(m[bnd][0], r0);
            mn[bnd][1] = fmaxf(m[bnd][1], r1);
            alpha[bnd][0] = ex2f((m[bnd][0] - mn[bnd][0]) * SCALE_LOG2E);
            alpha[bnd][1] = ex2f((m[bnd][1] - mn[bnd][1]) * SCALE_LOG2E);
            m[bnd][0] = mn[bnd][0]; m[bnd][1] = mn[bnd][1];
        }

#pragma unroll
        for (int bnd = 0; bnd < 2; ++bnd) {
            float rs0 = 0.0f, rs1 = 0.0f;
            float* pr0 = sP + (w * 32 + bnd * 16 + g) * STP;
            float* pr1 = pr0 + 8 * STP;
#pragma unroll
            for (int n0 = 0; n0 < 8; ++n0) {
                uint32_t u0 = cvt_tf32(ex2f((acc_s[bnd][n0][0] - mn[bnd][0]) * SCALE_LOG2E));
                uint32_t u1 = cvt_tf32(ex2f((acc_s[bnd][n0][1] - mn[bnd][0]) * SCALE_LOG2E));
                uint32_t u2 = cvt_tf32(ex2f((acc_s[bnd][n0][2] - mn[bnd][1]) * SCALE_LOG2E));
                uint32_t u3 = cvt_tf32(ex2f((acc_s[bnd][n0][3] - mn[bnd][1]) * SCALE_LOG2E));
                float p0 = __uint_as_float(u0), p1 = __uint_as_float(u1);
                float p2 = __uint_as_float(u2), p3 = __uint_as_float(u3);
                rs0 += p0 + p1;  rs1 += p2 + p3;
                *(float2*)(pr0 + n0 * 8 + 2 * tg) = make_float2(p0, p1);
                *(float2*)(pr1 + n0 * 8 + 2 * tg) = make_float2(p2, p3);
                acc_o[bnd][n0][0] *= alpha[bnd][0];
                acc_o[bnd][n0][1] *= alpha[bnd][0];
                acc_o[bnd][n0][2] *= alpha[bnd][1];
                acc_o[bnd][n0][3] *= alpha[bnd][1];
            }
            rs0 += __shfl_xor_sync(0xffffffffu, rs0, 1);
            rs0 += __shfl_xor_sync(0xffffffffu, rs0, 2);
            rs1 += __shfl_xor_sync(0xffffffffu, rs1, 1);
            rs1 += __shfl_xor_sync(0xffffffffu, rs1, 2);
            l[bnd][0] = l[bnd][0] * alpha[bnd][0] + rs0;
            l[bnd][1] = l[bnd][1] * alpha[bnd][1] + rs1;
        }
        __syncwarp();   // P rows are warp-private; make STS visible to lanes

        // ---- GEMM2: O += P @ V ----
        uint32_t pa[2][8][4];
#pragma unroll
        for (int bnd = 0; bnd < 2; ++bnd) {
            const float* pr0 = sP + (w * 32 + bnd * 16 + g) * STP;
            const float* pr1 = pr0 + 8 * STP;
#pragma unroll
            for (int kk = 0; kk < 8; ++kk) {
                pa[bnd][kk][0] = __float_as_uint(pr0[kk * 8 + tg]);
                pa[bnd][kk][1] = __float_as_uint(pr1[kk * 8 + tg]);
                pa[bnd][kk][2] = __float_as_uint(pr0[kk * 8 + tg + 4]);
                pa[bnd][kk][3] = __float_as_uint(pr1[kk * 8 + tg + 4]);
            }
        }
#pragma unroll
        for (int n0 = 0; n0 < 8; ++n0) {
            const float* vb = svb + tg * STV + n0 * 8 + g;
#pragma unroll
            for (int kk = 0; kk < 8; ++kk) {
                uint32_t b0 = cvt_tf32(vb[(kk * 8) * STV]);
                uint32_t b1 = cvt_tf32(vb[(kk * 8 + 4) * STV]);
                mma_tf32(acc_o[0][n0], pa[0][kk], b0, b1);
                mma_tf32(acc_o[1][n0], pa[1][kk], b0, b1);
            }
        }
    }

    // ---- epilogue: normalize and store ----
    float* og = o + hoff + (size_t)qt * BR * HD;
#pragma unroll
    for (int bnd = 0; bnd < 2; ++bnd) {
        float rl0 = 1.0f / l[bnd][0];
        float rl1 = 1.0f / l[bnd][1];
        float* or0 = og + (w * 32 + bnd * 16 + g) * HD;
        float* or1 = or0 + 8 * HD;
#pragma unroll
        for (int n0 = 0; n0 < 8; ++n0) {
            *(float2*)(or0 + n0 * 8 + 2 * tg) =
                make_float2(acc_o[bnd][n0][0] * rl0, acc_o[bnd][n0][1] * rl0);
            *(float2*)(or1 + n0 * 8 + 2 * tg) =
                make_float2(acc_o[bnd][n0][2] * rl1, acc_o[bnd][n0][3] * rl1);
        }
    }
}

extern "C" void kernel_launch(void* const* d_in, const int* in_sizes, int n_in,
                              void* d_out, int out_size) {
    const float* q = (const float*)d_in[0];
    const float* k = (const float*)d_in[1];
    const float* v = (const float*)d_in[2];
    float* o = (float*)d_out;

    const int smem_bytes = (2 * 64 * STK + 2 * 64 * STV + BR * STP) * (int)sizeof(float);
    cudaFuncSetAttribute(fa_tf32_kernel,
                         cudaFuncAttributeMaxDynamicSharedMemorySize, smem_bytes);

    dim3 grid(SEQ / BR, NBH);   // 16 x 64 = 1024 CTAs
    fa_tf32_kernel<<<grid, NTHREADS, smem_bytes>>>(q, k, v, o);
}